// round 1
// baseline (speedup 1.0000x reference)
#include <cuda_runtime.h>

typedef unsigned long long u64;

// ---- packed f32x2 helpers (sm_100+ packed fp32 pipe) ----
__device__ __forceinline__ u64 pk2(float a, float b) {
    u64 r; asm("mov.b64 %0,{%1,%2};" : "=l"(r) : "f"(a), "f"(b)); return r;
}
__device__ __forceinline__ u64 bc2(float a) {
    u64 r; asm("mov.b64 %0,{%1,%1};" : "=l"(r) : "f"(a)); return r;
}
__device__ __forceinline__ void upk2(u64 v, float& a, float& b) {
    asm("mov.b64 {%0,%1},%2;" : "=f"(a), "=f"(b) : "l"(v));
}
__device__ __forceinline__ u64 f2fma(u64 a, u64 b, u64 c) {
    u64 d; asm("fma.rn.f32x2 %0,%1,%2,%3;" : "=l"(d) : "l"(a), "l"(b), "l"(c)); return d;
}
__device__ __forceinline__ u64 f2mul(u64 a, u64 b) {
    u64 d; asm("mul.rn.f32x2 %0,%1,%2;" : "=l"(d) : "l"(a), "l"(b)); return d;
}
__device__ __forceinline__ u64 f2add(u64 a, u64 b) {
    u64 d; asm("add.rn.f32x2 %0,%1,%2;" : "=l"(d) : "l"(a), "l"(b)); return d;
}
__device__ __forceinline__ u64 f2neg(u64 a) { return a ^ 0x8000000080000000ULL; }
__device__ __forceinline__ u64 f2sub(u64 a, u64 b) { return f2add(a, f2neg(b)); }

// Gate params: layer0: 4 qubits x 8 floats (u00r,u00i,u01r,u01i,u10r,u10i,u11r,u11i)
//              where U = RZ(w1) @ RY(w0);  layer1: 4 qubits x (cRY, sRY).
__device__ __align__(16) float g_gp[40];

__global__ void qml_precompute(const float* __restrict__ w) {
    int i = threadIdx.x;
    if (i < 4) {
        // layer 0, qubit i
        float ry = w[i * 2 + 0], rz = w[i * 2 + 1];
        float s, c, zs, zc;
        sincosf(0.5f * ry, &s, &c);
        sincosf(0.5f * rz, &zs, &zc);
        // em = zc - i zs, ep = zc + i zs
        float* o = g_gp + i * 8;
        o[0] = c * zc;  o[1] = -c * zs;   // u00 = c*em
        o[2] = -s * zc; o[3] = s * zs;    // u01 = -s*em
        o[4] = s * zc;  o[5] = s * zs;    // u10 = s*ep
        o[6] = c * zc;  o[7] = c * zs;    // u11 = c*ep
    } else if (i < 8) {
        int q = i - 4;
        float ry = w[(4 + q) * 2 + 0];
        float s, c;
        sincosf(0.5f * ry, &s, &c);
        g_gp[32 + q * 2]     = c;
        g_gp[32 + q * 2 + 1] = s;
    }
}

__global__ void __launch_bounds__(128)
qml_main(const float* __restrict__ x, float* __restrict__ out, int B) {
    int tid = blockIdx.x * blockDim.x + threadIdx.x;
    int b0 = tid * 2;
    if (b0 >= B) return;

    // ---- gate params (uniform, L1-broadcast) ----
    float gp[40];
    {
        const float4* g4 = reinterpret_cast<const float4*>(g_gp);
#pragma unroll
        for (int i = 0; i < 10; i++) {
            float4 v = g4[i];
            gp[i * 4 + 0] = v.x; gp[i * 4 + 1] = v.y;
            gp[i * 4 + 2] = v.z; gp[i * 4 + 3] = v.w;
        }
    }

    // ---- per-sample RX angles (shared by both layers) ----
    const float4* xg = reinterpret_cast<const float4*>(x);
    float4 xa = xg[b0];
    float4 xb = xg[b0 + 1];
    float caA[4], saA[4], caB[4], saB[4];
    __sincosf(0.5f * xa.x, &saA[0], &caA[0]);
    __sincosf(0.5f * xa.y, &saA[1], &caA[1]);
    __sincosf(0.5f * xa.z, &saA[2], &caA[2]);
    __sincosf(0.5f * xa.w, &saA[3], &caA[3]);
    __sincosf(0.5f * xb.x, &saB[0], &caB[0]);
    __sincosf(0.5f * xb.y, &saB[1], &caB[1]);
    __sincosf(0.5f * xb.z, &saB[2], &caB[2]);
    __sincosf(0.5f * xb.w, &saB[3], &caB[3]);

    u64 cx2[4], sx2[4];
#pragma unroll
    for (int q = 0; q < 4; q++) {
        cx2[q] = pk2(caA[q], caB[q]);
        sx2[q] = pk2(saA[q], saB[q]);
    }

    // ---- layer 1: product state per qubit: v = (RZ@RY) @ RX(x) @ |0> ----
    // RX|0> = (cx, -i*sx); v0 = u00*cx + u01*(-i sx); v1 = u10*cx + u11*(-i sx)
    u64 vr[4][2], vi[4][2];
#pragma unroll
    for (int q = 0; q < 4; q++) {
        const float* u = gp + q * 8;
        vr[q][0] = f2fma(bc2(u[3]),  sx2[q], f2mul(bc2(u[0]), cx2[q])); // u00r*c + u01i*s
        vi[q][0] = f2fma(bc2(-u[2]), sx2[q], f2mul(bc2(u[1]), cx2[q])); // u00i*c - u01r*s
        vr[q][1] = f2fma(bc2(u[7]),  sx2[q], f2mul(bc2(u[4]), cx2[q])); // u10r*c + u11i*s
        vi[q][1] = f2fma(bc2(-u[6]), sx2[q], f2mul(bc2(u[5]), cx2[q])); // u10i*c - u11r*s
    }

    // ---- tensor product expansion to 16 amplitudes, k = q0*8+q1*4+q2*2+q3 ----
    u64 re[16], im[16];
    {
        u64 r2[4], i2[4];
        u64 n1[2] = { f2neg(vi[1][0]), f2neg(vi[1][1]) };
#pragma unroll
        for (int a = 0; a < 2; a++)
#pragma unroll
            for (int b = 0; b < 2; b++) {
                int k = a * 2 + b;
                r2[k] = f2fma(vi[0][a], n1[b],    f2mul(vr[0][a], vr[1][b]));
                i2[k] = f2fma(vi[0][a], vr[1][b], f2mul(vr[0][a], vi[1][b]));
            }
        u64 r3[8], i3[8];
        u64 n2[2] = { f2neg(vi[2][0]), f2neg(vi[2][1]) };
#pragma unroll
        for (int j = 0; j < 4; j++)
#pragma unroll
            for (int b = 0; b < 2; b++) {
                int k = j * 2 + b;
                r3[k] = f2fma(i2[j], n2[b],    f2mul(r2[j], vr[2][b]));
                i3[k] = f2fma(i2[j], vr[2][b], f2mul(r2[j], vi[2][b]));
            }
        u64 n3[2] = { f2neg(vi[3][0]), f2neg(vi[3][1]) };
#pragma unroll
        for (int j = 0; j < 8; j++)
#pragma unroll
            for (int b = 0; b < 2; b++) {
                int k = j * 2 + b;
                re[k] = f2fma(i3[j], n3[b],    f2mul(r3[j], vr[3][b]));
                im[k] = f2fma(i3[j], vr[3][b], f2mul(r3[j], vi[3][b]));
            }
    }

    // ---- layer-1 CNOT chain: pure basis-state permutation (register renames) ----
#pragma unroll
    for (int c = 0; c < 3; c++) {
        int bcm = 8 >> c, btm = 8 >> (c + 1);
#pragma unroll
        for (int k = 0; k < 16; k++)
            if ((k & bcm) && !(k & btm)) {
                u64 tr = re[k]; re[k] = re[k | btm]; re[k | btm] = tr;
                u64 ti = im[k]; im[k] = im[k | btm]; im[k | btm] = ti;
            }
    }

    // ---- layer 2: RX per qubit (per-sample coeffs) ----
#pragma unroll
    for (int q = 0; q < 4; q++) {
        int bq = 8 >> q;
        u64 cx = cx2[q], sx = sx2[q], nsx = f2neg(sx2[q]);
#pragma unroll
        for (int k = 0; k < 16; k++)
            if (!(k & bq)) {
                int k1 = k | bq;
                u64 n0r = f2fma(sx,  im[k1], f2mul(cx, re[k]));
                u64 n0i = f2fma(nsx, re[k1], f2mul(cx, im[k]));
                u64 n1r = f2fma(sx,  im[k],  f2mul(cx, re[k1]));
                u64 n1i = f2fma(nsx, re[k],  f2mul(cx, im[k1]));
                re[k] = n0r; im[k] = n0i; re[k1] = n1r; im[k1] = n1i;
            }
    }

    // ---- layer 2: RY per qubit (real 2x2; layer-2 RZ dropped: diagonal phase
    //      is invisible to |amp|^2 through the CNOT permutation) ----
#pragma unroll
    for (int q = 0; q < 4; q++) {
        int bq = 8 >> q;
        u64 c2 = bc2(gp[32 + 2 * q]);
        u64 s2 = bc2(gp[33 + 2 * q]);
        u64 ns2 = bc2(-gp[33 + 2 * q]);
#pragma unroll
        for (int k = 0; k < 16; k++)
            if (!(k & bq)) {
                int k1 = k | bq;
                u64 n0r = f2fma(ns2, re[k1], f2mul(c2, re[k]));
                u64 n0i = f2fma(ns2, im[k1], f2mul(c2, im[k]));
                u64 n1r = f2fma(c2, re[k1], f2mul(s2, re[k]));
                u64 n1i = f2fma(c2, im[k1], f2mul(s2, im[k]));
                re[k] = n0r; im[k] = n0i; re[k1] = n1r; im[k1] = n1i;
            }
    }

    // ---- probabilities ----
    u64 p[16];
#pragma unroll
    for (int k = 0; k < 16; k++)
        p[k] = f2fma(re[k], re[k], f2mul(im[k], im[k]));

    // ---- layer-2 CNOTs folded into measurement parities:
    //   Z0: (-1)^{b0}, Z1: (-1)^{b0^b1}, Z2: (-1)^{b0^b1^b2}, Z3: (-1)^{b0^b1^b2^b3}
    u64 s01[8], d01[8];
#pragma unroll
    for (int j = 0; j < 8; j++) {
        s01[j] = f2add(p[2 * j], p[2 * j + 1]);
        d01[j] = f2sub(p[2 * j], p[2 * j + 1]);
    }
    // Z3: parity of j (3 bits): + - - + - + + -
    u64 Z3 = f2sub(f2add(f2add(d01[0], d01[3]), f2add(d01[5], d01[6])),
                   f2add(f2add(d01[1], d01[2]), f2add(d01[4], d01[7])));
    u64 sq[4], dq[4];
#pragma unroll
    for (int m = 0; m < 4; m++) {
        sq[m] = f2add(s01[2 * m], s01[2 * m + 1]);
        dq[m] = f2sub(s01[2 * m], s01[2 * m + 1]);
    }
    u64 Z2 = f2sub(f2add(dq[0], dq[3]), f2add(dq[1], dq[2]));
    u64 Z1 = f2sub(f2add(sq[0], sq[3]), f2add(sq[1], sq[2]));
    u64 Z0 = f2sub(f2add(sq[0], sq[1]), f2add(sq[2], sq[3]));

    // ---- unpack lanes and store [B,4] as float4 per sample ----
    float z0a, z0b, z1a, z1b, z2a, z2b, z3a, z3b;
    upk2(Z0, z0a, z0b); upk2(Z1, z1a, z1b);
    upk2(Z2, z2a, z2b); upk2(Z3, z3a, z3b);
    float4* o4 = reinterpret_cast<float4*>(out);
    o4[b0]     = make_float4(z0a, z1a, z2a, z3a);
    o4[b0 + 1] = make_float4(z0b, z1b, z2b, z3b);
}

extern "C" void kernel_launch(void* const* d_in, const int* in_sizes, int n_in,
                              void* d_out, int out_size) {
    const float* x = (const float*)d_in[0];       // [B,4] float32
    const float* w = (const float*)d_in[1];       // [2,4,2] float32
    float* out = (float*)d_out;                   // [B,4] float32
    int B = in_sizes[0] / 4;

    qml_precompute<<<1, 8>>>(w);
    int nthreads = (B + 1) / 2;
    int block = 128;
    int grid = (nthreads + block - 1) / block;
    qml_main<<<grid, block>>>(x, out, B);
}

// round 2
// speedup vs baseline: 1.0654x; 1.0654x over previous
#include <cuda_runtime.h>

typedef unsigned long long u64;
typedef unsigned int u32;

// ---- packed f32x2 helpers ----
__device__ __forceinline__ u64 pk2(float a, float b) {
    u64 r; asm("mov.b64 %0,{%1,%2};" : "=l"(r) : "f"(a), "f"(b)); return r;
}
__device__ __forceinline__ void upk2(u64 v, float& a, float& b) {
    asm("mov.b64 {%0,%1},%2;" : "=f"(a), "=f"(b) : "l"(v));
}
__device__ __forceinline__ u64 f2fma(u64 a, u64 b, u64 c) {
    u64 d; asm("fma.rn.f32x2 %0,%1,%2,%3;" : "=l"(d) : "l"(a), "l"(b), "l"(c)); return d;
}
__device__ __forceinline__ u64 f2mul(u64 a, u64 b) {
    u64 d; asm("mul.rn.f32x2 %0,%1,%2;" : "=l"(d) : "l"(a), "l"(b)); return d;
}
__device__ __forceinline__ u64 f2add(u64 a, u64 b) {
    u64 d; asm("add.rn.f32x2 %0,%1,%2;" : "=l"(d) : "l"(a), "l"(b)); return d;
}

// Gate params, each float duplicated into both f32x2 lanes (u64).
// [8q+0..7], q=0..3 (layer1): u00r, u00i, u01i, -u01r, u10r, u10i, u11i, -u11r
//   where U = RZ(w[q,1]) @ RY(w[q,0])
// [32+3q+0..2], q=0..3 (layer2): cos(w/2), sin(w/2), -sin(w/2) of RY weight
__device__ __align__(16) u64 g_gpu[48];

__device__ __forceinline__ u64 dupf(float v) {
    u32 b = __float_as_uint(v);
    return ((u64)b << 32) | (u64)b;
}

__global__ void qml_precompute(const float* __restrict__ w) {
    if (threadIdx.x == 0) {
        for (int q = 0; q < 4; q++) {
            float ry = w[q * 2 + 0], rz = w[q * 2 + 1];
            float s, c, zs, zc;
            sincosf(0.5f * ry, &s, &c);
            sincosf(0.5f * rz, &zs, &zc);
            // U = RZ@RY: u00 = c*zc - i c*zs; u01 = -s*zc + i s*zs;
            //            u10 = s*zc + i s*zs; u11 = c*zc + i c*zs
            u64* o = g_gpu + q * 8;
            o[0] = dupf(c * zc);     // u00r
            o[1] = dupf(-c * zs);    // u00i
            o[2] = dupf(s * zs);     // u01i
            o[3] = dupf(s * zc);     // -u01r = -(-s*zc)
            o[4] = dupf(s * zc);     // u10r
            o[5] = dupf(s * zs);     // u10i
            o[6] = dupf(c * zs);     // u11i
            o[7] = dupf(-c * zc);    // -u11r
        }
        for (int q = 0; q < 4; q++) {
            float ry = w[(4 + q) * 2 + 0];
            float s, c;
            sincosf(0.5f * ry, &s, &c);
            g_gpu[32 + 3 * q + 0] = dupf(c);
            g_gpu[32 + 3 * q + 1] = dupf(s);
            g_gpu[32 + 3 * q + 2] = dupf(-s);
        }
    }
}

__global__ void __launch_bounds__(128)
qml_main(const float* __restrict__ x, float* __restrict__ out, int B) {
    int tid = blockIdx.x * blockDim.x + threadIdx.x;
    int b0 = tid * 2;
    if (b0 >= B) return;

    const u64 m1 = 0xBF800000BF800000ULL;  // {-1.0f, -1.0f}

    // ---- per-sample RX half-angle sin/cos (shared by both layers) ----
    const float4* xg = reinterpret_cast<const float4*>(x);
    float4 xa = xg[b0];
    float4 xb = xg[b0 + 1];
    float caA[4], saA[4], caB[4], saB[4];
    __sincosf(0.5f * xa.x, &saA[0], &caA[0]);
    __sincosf(0.5f * xa.y, &saA[1], &caA[1]);
    __sincosf(0.5f * xa.z, &saA[2], &caA[2]);
    __sincosf(0.5f * xa.w, &saA[3], &caA[3]);
    __sincosf(0.5f * xb.x, &saB[0], &caB[0]);
    __sincosf(0.5f * xb.y, &saB[1], &caB[1]);
    __sincosf(0.5f * xb.z, &saB[2], &caB[2]);
    __sincosf(0.5f * xb.w, &saB[3], &caB[3]);

    u64 cx2[4], sx2[4];
#pragma unroll
    for (int q = 0; q < 4; q++) {
        cx2[q] = pk2(caA[q], caB[q]);
        sx2[q] = pk2(saA[q], saB[q]);
    }

    // ---- layer-1 single-qubit factors: v = (RZ@RY) @ RX(x) @ |0> ----
    u64 vr[4][2], vi[4][2];
#pragma unroll
    for (int q = 0; q < 4; q++) {
        const u64* u = g_gpu + q * 8;
        vr[q][0] = f2fma(u[2], sx2[q], f2mul(u[0], cx2[q]));
        vi[q][0] = f2fma(u[3], sx2[q], f2mul(u[1], cx2[q]));
        vr[q][1] = f2fma(u[6], sx2[q], f2mul(u[4], cx2[q]));
        vi[q][1] = f2fma(u[7], sx2[q], f2mul(u[5], cx2[q]));
    }

    // ==== Layer-2 RX gates commuted BACKWARD through layer-1's CNOT chain:
    //   RX3 stays RX3; RX2 -> RXX(2,3); RX1 -> RXX(1,2); RX0 -> RXX(0,1),
    //   all applied to the (partially expanded) product state BEFORE the CNOTs.
    //   (X on CNOT target commutes; X on control picks up X on target.) ====

    // RX(x3) applied to qubit-3 factor (8 ops instead of 64)
    u64 wr[2], wi[2];
    {
        u64 c = cx2[3], s = sx2[3], ns = f2mul(s, m1);
        wr[0] = f2fma(s,  vi[3][1], f2mul(c, vr[3][0]));
        wi[0] = f2fma(ns, vr[3][1], f2mul(c, vi[3][0]));
        wr[1] = f2fma(s,  vi[3][0], f2mul(c, vr[3][1]));
        wi[1] = f2fma(ns, vr[3][0], f2mul(c, vi[3][1]));
    }

    // Psi23 = v2 (x) w, then RXX(x2) on it (mask 3: flips both bits)
    u64 Qr[4], Qi[4];
    {
        u64 Pr[4], Pi[4];
        u64 nv2i0 = f2mul(vi[2][0], m1), nv2i1 = f2mul(vi[2][1], m1);
#pragma unroll
        for (int a = 0; a < 2; a++) {
            u64 ar = vr[2][a], ai = vi[2][a], nai = (a == 0) ? nv2i0 : nv2i1;
#pragma unroll
            for (int b = 0; b < 2; b++) {
                int j = a * 2 + b;
                Pr[j] = f2fma(nai, wi[b], f2mul(ar, wr[b]));
                Pi[j] = f2fma(ai,  wr[b], f2mul(ar, wi[b]));
            }
        }
        u64 c = cx2[2], s = sx2[2], ns = f2mul(s, m1);
#pragma unroll
        for (int k = 0; k < 4; k++) {
            Qr[k] = f2fma(s,  Pi[k ^ 3], f2mul(c, Pr[k]));
            Qi[k] = f2fma(ns, Pr[k ^ 3], f2mul(c, Pi[k]));
        }
    }

    // Phi123 = v1 (x) Q, then RXX(x1) (mask 6: flips q1,q2). Fused pairwise.
    u64 Fr[8], Fi[8];
    {
        u64 nv1i0 = f2mul(vi[1][0], m1), nv1i1 = f2mul(vi[1][1], m1);
        u64 c = cx2[1], s = sx2[1], ns = f2mul(s, m1);
#pragma unroll
        for (int j = 0; j < 4; j++) {
            int j2 = j ^ 6;             // partner index
            int a1 = j >> 2, t1 = j & 3;
            int a2 = j2 >> 2, t2 = j2 & 3;
            u64 p1r = f2fma((a1 ? nv1i1 : nv1i0), Qi[t1], f2mul(vr[1][a1], Qr[t1]));
            u64 p1i = f2fma(vi[1][a1],            Qr[t1], f2mul(vr[1][a1], Qi[t1]));
            u64 p2r = f2fma((a2 ? nv1i1 : nv1i0), Qi[t2], f2mul(vr[1][a2], Qr[t2]));
            u64 p2i = f2fma(vi[1][a2],            Qr[t2], f2mul(vr[1][a2], Qi[t2]));
            Fr[j]  = f2fma(s,  p2i, f2mul(c, p1r));
            Fi[j]  = f2fma(ns, p2r, f2mul(c, p1i));
            Fr[j2] = f2fma(s,  p1i, f2mul(c, p2r));
            Fi[j2] = f2fma(ns, p1r, f2mul(c, p2i));
        }
    }

    // Full state = v0 (x) F, then RXX(x0) (mask 12: flips q0,q1). Fused pairwise.
    u64 re[16], im[16];
    {
        u64 nv0i0 = f2mul(vi[0][0], m1), nv0i1 = f2mul(vi[0][1], m1);
        u64 c = cx2[0], s = sx2[0], ns = f2mul(s, m1);
#pragma unroll
        for (int t = 0; t < 8; t++) {
            int k1 = t;                 // a=0
            int k2 = 8 + (t ^ 4);       // partner: a=1, t^4
            int t2 = t ^ 4;
            u64 p1r = f2fma(nv0i0,    Fi[t],  f2mul(vr[0][0], Fr[t]));
            u64 p1i = f2fma(vi[0][0], Fr[t],  f2mul(vr[0][0], Fi[t]));
            u64 p2r = f2fma(nv0i1,    Fi[t2], f2mul(vr[0][1], Fr[t2]));
            u64 p2i = f2fma(vi[0][1], Fr[t2], f2mul(vr[0][1], Fi[t2]));
            re[k1] = f2fma(s,  p2i, f2mul(c, p1r));
            im[k1] = f2fma(ns, p2r, f2mul(c, p1i));
            re[k2] = f2fma(s,  p1i, f2mul(c, p2r));
            im[k2] = f2fma(ns, p1r, f2mul(c, p2i));
        }
    }

    // ---- layer-1 CNOT chain: pure basis permutation (register renames) ----
#pragma unroll
    for (int c = 0; c < 3; c++) {
        int bcm = 8 >> c, btm = 8 >> (c + 1);
#pragma unroll
        for (int k = 0; k < 16; k++)
            if ((k & bcm) && !(k & btm)) {
                u64 tr = re[k]; re[k] = re[k | btm]; re[k | btm] = tr;
                u64 ti = im[k]; im[k] = im[k | btm]; im[k | btm] = ti;
            }
    }

    // ---- layer-2 RY per qubit (real 2x2; layer-2 RZ dropped: diagonal phase
    //      is invisible to |amp|^2 through the final CNOT permutation) ----
#pragma unroll
    for (int q = 0; q < 4; q++) {
        int bq = 8 >> q;
        u64 c2  = g_gpu[32 + 3 * q + 0];
        u64 s2  = g_gpu[32 + 3 * q + 1];
        u64 ns2 = g_gpu[32 + 3 * q + 2];
#pragma unroll
        for (int k = 0; k < 16; k++)
            if (!(k & bq)) {
                int k1 = k | bq;
                u64 n0r = f2fma(ns2, re[k1], f2mul(c2, re[k]));
                u64 n0i = f2fma(ns2, im[k1], f2mul(c2, im[k]));
                u64 n1r = f2fma(c2, re[k1], f2mul(s2, re[k]));
                u64 n1i = f2fma(c2, im[k1], f2mul(s2, im[k]));
                re[k] = n0r; im[k] = n0i; re[k1] = n1r; im[k1] = n1i;
            }
    }

    // ---- probabilities ----
    u64 p[16];
#pragma unroll
    for (int k = 0; k < 16; k++)
        p[k] = f2fma(re[k], re[k], f2mul(im[k], im[k]));

    // ---- layer-2 CNOTs folded into measurement parities (Walsh):
    //   Z0:(-1)^{b0}  Z1:(-1)^{b0^b1}  Z2:(-1)^{b0^b1^b2}  Z3:(-1)^{b0..b3}
    //   subs done as fma(b, -1, a): one FMA-pipe slot instead of 2xLOP3+ADD
    u64 s01[8], d01[8];
#pragma unroll
    for (int j = 0; j < 8; j++) {
        s01[j] = f2add(p[2 * j], p[2 * j + 1]);
        d01[j] = f2fma(p[2 * j + 1], m1, p[2 * j]);
    }
    u64 z3p = f2add(f2add(d01[0], d01[3]), f2add(d01[5], d01[6]));
    u64 z3m = f2add(f2add(d01[1], d01[2]), f2add(d01[4], d01[7]));
    u64 Z3 = f2fma(z3m, m1, z3p);

    u64 sq[4], dq[4];
#pragma unroll
    for (int m = 0; m < 4; m++) {
        sq[m] = f2add(s01[2 * m], s01[2 * m + 1]);
        dq[m] = f2fma(s01[2 * m + 1], m1, s01[2 * m]);
    }
    u64 Z2 = f2fma(f2add(dq[1], dq[2]), m1, f2add(dq[0], dq[3]));
    u64 Z1 = f2fma(f2add(sq[1], sq[2]), m1, f2add(sq[0], sq[3]));
    u64 Z0 = f2fma(f2add(sq[2], sq[3]), m1, f2add(sq[0], sq[1]));

    // ---- unpack lanes and store [B,4] as float4 per sample ----
    float z0a, z0b, z1a, z1b, z2a, z2b, z3a, z3b;
    upk2(Z0, z0a, z0b); upk2(Z1, z1a, z1b);
    upk2(Z2, z2a, z2b); upk2(Z3, z3a, z3b);
    float4* o4 = reinterpret_cast<float4*>(out);
    o4[b0]     = make_float4(z0a, z1a, z2a, z3a);
    o4[b0 + 1] = make_float4(z0b, z1b, z2b, z3b);
}

extern "C" void kernel_launch(void* const* d_in, const int* in_sizes, int n_in,
                              void* d_out, int out_size) {
    const float* x = (const float*)d_in[0];       // [B,4] float32
    const float* w = (const float*)d_in[1];       // [2,4,2] float32
    float* out = (float*)d_out;                   // [B,4] float32
    int B = in_sizes[0] / 4;

    qml_precompute<<<1, 32>>>(w);
    int nthreads = (B + 1) / 2;
    int block = 128;
    int grid = (nthreads + block - 1) / block;
    qml_main<<<grid, block>>>(x, out, B);
}

// round 3
// speedup vs baseline: 1.0780x; 1.0118x over previous
#include <cuda_runtime.h>

typedef unsigned long long u64;
typedef unsigned int u32;

// ---- packed f32x2 helpers ----
__device__ __forceinline__ u64 pk2(float a, float b) {
    u64 r; asm("mov.b64 %0,{%1,%2};" : "=l"(r) : "f"(a), "f"(b)); return r;
}
__device__ __forceinline__ void upk2(u64 v, float& a, float& b) {
    asm("mov.b64 {%0,%1},%2;" : "=f"(a), "=f"(b) : "l"(v));
}
__device__ __forceinline__ u64 f2fma(u64 a, u64 b, u64 c) {
    u64 d; asm("fma.rn.f32x2 %0,%1,%2,%3;" : "=l"(d) : "l"(a), "l"(b), "l"(c)); return d;
}
__device__ __forceinline__ u64 f2mul(u64 a, u64 b) {
    u64 d; asm("mul.rn.f32x2 %0,%1,%2;" : "=l"(d) : "l"(a), "l"(b)); return d;
}
__device__ __forceinline__ u64 f2add(u64 a, u64 b) {
    u64 d; asm("add.rn.f32x2 %0,%1,%2;" : "=l"(d) : "l"(a), "l"(b)); return d;
}

// Gate params, each float duplicated into both f32x2 lanes (u64).
// [8q+0..7], q=0..3 (layer1): u00r, u00i, u01i, -u01r, u10r, u10i, u11i, -u11r
//   where U = RZ(w[q,1]) @ RY(w[q,0])
// [32+3q+0..2], q=0..2 (layer2 RY q0..q2): cos(w/2), sin(w/2), -sin(w/2)
// [41] A3 = cos(w3)   [42] B3 = -2*sin(w3)   (RY3 folded into quadratics)
__device__ __align__(16) u64 g_gpu[48];

__device__ __forceinline__ u64 dupf(float v) {
    u32 b = __float_as_uint(v);
    return ((u64)b << 32) | (u64)b;
}

__global__ void qml_precompute(const float* __restrict__ w) {
    if (threadIdx.x == 0) {
        for (int q = 0; q < 4; q++) {
            float ry = w[q * 2 + 0], rz = w[q * 2 + 1];
            float s, c, zs, zc;
            sincosf(0.5f * ry, &s, &c);
            sincosf(0.5f * rz, &zs, &zc);
            u64* o = g_gpu + q * 8;
            o[0] = dupf(c * zc);     // u00r
            o[1] = dupf(-c * zs);    // u00i
            o[2] = dupf(s * zs);     // u01i
            o[3] = dupf(s * zc);     // -u01r
            o[4] = dupf(s * zc);     // u10r
            o[5] = dupf(s * zs);     // u10i
            o[6] = dupf(c * zs);     // u11i
            o[7] = dupf(-c * zc);    // -u11r
        }
        for (int q = 0; q < 3; q++) {
            float ry = w[(4 + q) * 2 + 0];
            float s, c;
            sincosf(0.5f * ry, &s, &c);
            g_gpu[32 + 3 * q + 0] = dupf(c);
            g_gpu[32 + 3 * q + 1] = dupf(s);
            g_gpu[32 + 3 * q + 2] = dupf(-s);
        }
        {   // qubit-3 RY folded into measurement quadratics:
            // d01 = cos(w)*(|a0|^2-|a1|^2) - 4*c*s*(r0r1+i0i1)
            float ry = w[7 * 2 + 0];
            float s, c;
            sincosf(0.5f * ry, &s, &c);
            g_gpu[41] = dupf(c * c - s * s);   // cos(w3)
            g_gpu[42] = dupf(-4.0f * c * s);   // -2 sin(w3) * 2
        }
    }
}

__global__ void __launch_bounds__(128, 5)
qml_main(const float* __restrict__ x, float* __restrict__ out, int npairs) {
    const u64 m1 = 0xBF800000BF800000ULL;  // {-1.0f, -1.0f}
    const float4* xg = reinterpret_cast<const float4*>(x);
    float4* o4 = reinterpret_cast<float4*>(out);

    int stride = gridDim.x * blockDim.x;
    int idx = blockIdx.x * blockDim.x + threadIdx.x;
    if (idx >= npairs) return;

    float4 xa = xg[2 * idx];
    float4 xb = xg[2 * idx + 1];

    while (true) {
        // ---- software-pipelined prefetch of next iteration's x ----
        int nidx = idx + stride;
        float4 nxa, nxb;
        bool more = nidx < npairs;
        if (more) {
            nxa = xg[2 * nidx];
            nxb = xg[2 * nidx + 1];
        }

        // ---- per-sample RX half-angle sin/cos (shared by both layers) ----
        float caA[4], saA[4], caB[4], saB[4];
        __sincosf(0.5f * xa.x, &saA[0], &caA[0]);
        __sincosf(0.5f * xa.y, &saA[1], &caA[1]);
        __sincosf(0.5f * xa.z, &saA[2], &caA[2]);
        __sincosf(0.5f * xa.w, &saA[3], &caA[3]);
        __sincosf(0.5f * xb.x, &saB[0], &caB[0]);
        __sincosf(0.5f * xb.y, &saB[1], &caB[1]);
        __sincosf(0.5f * xb.z, &saB[2], &caB[2]);
        __sincosf(0.5f * xb.w, &saB[3], &caB[3]);

        u64 cx2[4], sx2[4];
#pragma unroll
        for (int q = 0; q < 4; q++) {
            cx2[q] = pk2(caA[q], caB[q]);
            sx2[q] = pk2(saA[q], saB[q]);
        }

        // ---- layer-1 single-qubit factors: v = (RZ@RY) @ RX(x) @ |0> ----
        u64 vr[4][2], vi[4][2];
#pragma unroll
        for (int q = 0; q < 4; q++) {
            const u64* u = g_gpu + q * 8;
            vr[q][0] = f2fma(u[2], sx2[q], f2mul(u[0], cx2[q]));
            vi[q][0] = f2fma(u[3], sx2[q], f2mul(u[1], cx2[q]));
            vr[q][1] = f2fma(u[6], sx2[q], f2mul(u[4], cx2[q]));
            vi[q][1] = f2fma(u[7], sx2[q], f2mul(u[5], cx2[q]));
        }

        // ==== Layer-2 RX gates commuted backward through layer-1's CNOTs:
        //   RX3 stays; RX2->RXX(2,3); RX1->RXX(1,2); RX0->RXX(0,1). ====

        // RX(x3) on qubit-3 factor
        u64 wr[2], wi[2];
        {
            u64 c = cx2[3], s = sx2[3], ns = f2mul(s, m1);
            wr[0] = f2fma(s,  vi[3][1], f2mul(c, vr[3][0]));
            wi[0] = f2fma(ns, vr[3][1], f2mul(c, vi[3][0]));
            wr[1] = f2fma(s,  vi[3][0], f2mul(c, vr[3][1]));
            wi[1] = f2fma(ns, vr[3][0], f2mul(c, vi[3][1]));
        }

        // Psi23 = v2 (x) w, then RXX(x2) (mask 3)
        u64 Qr[4], Qi[4];
        {
            u64 Pr[4], Pi[4];
            u64 nv2i0 = f2mul(vi[2][0], m1), nv2i1 = f2mul(vi[2][1], m1);
#pragma unroll
            for (int a = 0; a < 2; a++) {
                u64 ar = vr[2][a], ai = vi[2][a], nai = (a == 0) ? nv2i0 : nv2i1;
#pragma unroll
                for (int b = 0; b < 2; b++) {
                    int j = a * 2 + b;
                    Pr[j] = f2fma(nai, wi[b], f2mul(ar, wr[b]));
                    Pi[j] = f2fma(ai,  wr[b], f2mul(ar, wi[b]));
                }
            }
            u64 c = cx2[2], s = sx2[2], ns = f2mul(s, m1);
#pragma unroll
            for (int k = 0; k < 4; k++) {
                Qr[k] = f2fma(s,  Pi[k ^ 3], f2mul(c, Pr[k]));
                Qi[k] = f2fma(ns, Pr[k ^ 3], f2mul(c, Pi[k]));
            }
        }

        // Phi123 = v1 (x) Q, then RXX(x1) (mask 6). Fused pairwise.
        u64 Fr[8], Fi[8];
        {
            u64 nv1i0 = f2mul(vi[1][0], m1), nv1i1 = f2mul(vi[1][1], m1);
            u64 c = cx2[1], s = sx2[1], ns = f2mul(s, m1);
#pragma unroll
            for (int j = 0; j < 4; j++) {
                int j2 = j ^ 6;
                int a1 = j >> 2, t1 = j & 3;
                int a2 = j2 >> 2, t2 = j2 & 3;
                u64 p1r = f2fma((a1 ? nv1i1 : nv1i0), Qi[t1], f2mul(vr[1][a1], Qr[t1]));
                u64 p1i = f2fma(vi[1][a1],            Qr[t1], f2mul(vr[1][a1], Qi[t1]));
                u64 p2r = f2fma((a2 ? nv1i1 : nv1i0), Qi[t2], f2mul(vr[1][a2], Qr[t2]));
                u64 p2i = f2fma(vi[1][a2],            Qr[t2], f2mul(vr[1][a2], Qi[t2]));
                Fr[j]  = f2fma(s,  p2i, f2mul(c, p1r));
                Fi[j]  = f2fma(ns, p2r, f2mul(c, p1i));
                Fr[j2] = f2fma(s,  p1i, f2mul(c, p2r));
                Fi[j2] = f2fma(ns, p1r, f2mul(c, p2i));
            }
        }

        // Full state = v0 (x) F, then RXX(x0) (mask 12). Fused pairwise.
        u64 re[16], im[16];
        {
            u64 nv0i0 = f2mul(vi[0][0], m1), nv0i1 = f2mul(vi[0][1], m1);
            u64 c = cx2[0], s = sx2[0], ns = f2mul(s, m1);
#pragma unroll
            for (int t = 0; t < 8; t++) {
                int k1 = t;
                int k2 = 8 + (t ^ 4);
                int t2 = t ^ 4;
                u64 p1r = f2fma(nv0i0,    Fi[t],  f2mul(vr[0][0], Fr[t]));
                u64 p1i = f2fma(vi[0][0], Fr[t],  f2mul(vr[0][0], Fi[t]));
                u64 p2r = f2fma(nv0i1,    Fi[t2], f2mul(vr[0][1], Fr[t2]));
                u64 p2i = f2fma(vi[0][1], Fr[t2], f2mul(vr[0][1], Fi[t2]));
                re[k1] = f2fma(s,  p2i, f2mul(c, p1r));
                im[k1] = f2fma(ns, p2r, f2mul(c, p1i));
                re[k2] = f2fma(s,  p1i, f2mul(c, p2r));
                im[k2] = f2fma(ns, p1r, f2mul(c, p2i));
            }
        }

        // ---- layer-1 CNOT chain: basis permutation (register renames) ----
#pragma unroll
        for (int c = 0; c < 3; c++) {
            int bcm = 8 >> c, btm = 8 >> (c + 1);
#pragma unroll
            for (int k = 0; k < 16; k++)
                if ((k & bcm) && !(k & btm)) {
                    u64 tr = re[k]; re[k] = re[k | btm]; re[k | btm] = tr;
                    u64 ti = im[k]; im[k] = im[k | btm]; im[k | btm] = ti;
                }
        }

        // ---- layer-2 RY for qubits 0..2 (real 2x2; RZ dropped) ----
#pragma unroll
        for (int q = 0; q < 3; q++) {
            int bq = 8 >> q;
            u64 c2  = g_gpu[32 + 3 * q + 0];
            u64 s2  = g_gpu[32 + 3 * q + 1];
            u64 ns2 = g_gpu[32 + 3 * q + 2];
#pragma unroll
            for (int k = 0; k < 16; k++)
                if (!(k & bq)) {
                    int k1 = k | bq;
                    u64 n0r = f2fma(ns2, re[k1], f2mul(c2, re[k]));
                    u64 n0i = f2fma(ns2, im[k1], f2mul(c2, im[k]));
                    u64 n1r = f2fma(c2, re[k1], f2mul(s2, re[k]));
                    u64 n1i = f2fma(c2, im[k1], f2mul(s2, im[k]));
                    re[k] = n0r; im[k] = n0i; re[k1] = n1r; im[k1] = n1i;
                }
        }

        // ---- qubit-3 RY folded into the quadratics:
        //   s01 = |a0|^2+|a1|^2   (rotation-invariant)
        //   d01 = cos(w3)*(|a0|^2-|a1|^2) - 4 c s * (r0r1 + i0i1)
        u64 s01[8], d01[8];
        {
            u64 A3 = g_gpu[41], B3 = g_gpu[42];
#pragma unroll
            for (int j = 0; j < 8; j++) {
                int k0 = 2 * j, k1 = 2 * j + 1;
                u64 q0 = f2fma(im[k0], im[k0], f2mul(re[k0], re[k0]));
                u64 q1 = f2fma(im[k1], im[k1], f2mul(re[k1], re[k1]));
                u64 xx = f2fma(im[k0], im[k1], f2mul(re[k0], re[k1]));
                s01[j] = f2add(q0, q1);
                u64 z  = f2fma(q1, m1, q0);
                d01[j] = f2fma(B3, xx, f2mul(A3, z));
            }
        }

        // ---- layer-2 CNOTs folded into measurement parities (Walsh) ----
        u64 z3p = f2add(f2add(d01[0], d01[3]), f2add(d01[5], d01[6]));
        u64 z3m = f2add(f2add(d01[1], d01[2]), f2add(d01[4], d01[7]));
        u64 Z3 = f2fma(z3m, m1, z3p);

        u64 sq[4], dq[4];
#pragma unroll
        for (int m = 0; m < 4; m++) {
            sq[m] = f2add(s01[2 * m], s01[2 * m + 1]);
            dq[m] = f2fma(s01[2 * m + 1], m1, s01[2 * m]);
        }
        u64 Z2 = f2fma(f2add(dq[1], dq[2]), m1, f2add(dq[0], dq[3]));
        u64 Z1 = f2fma(f2add(sq[1], sq[2]), m1, f2add(sq[0], sq[3]));
        u64 Z0 = f2fma(f2add(sq[2], sq[3]), m1, f2add(sq[0], sq[1]));

        // ---- unpack lanes and store ----
        float z0a, z0b, z1a, z1b, z2a, z2b, z3a, z3b;
        upk2(Z0, z0a, z0b); upk2(Z1, z1a, z1b);
        upk2(Z2, z2a, z2b); upk2(Z3, z3a, z3b);
        o4[2 * idx]     = make_float4(z0a, z1a, z2a, z3a);
        o4[2 * idx + 1] = make_float4(z0b, z1b, z2b, z3b);

        if (!more) break;
        idx = nidx;
        xa = nxa;
        xb = nxb;
    }
}

extern "C" void kernel_launch(void* const* d_in, const int* in_sizes, int n_in,
                              void* d_out, int out_size) {
    const float* x = (const float*)d_in[0];       // [B,4] float32
    const float* w = (const float*)d_in[1];       // [2,4,2] float32
    float* out = (float*)d_out;                   // [B,4] float32
    int B = in_sizes[0] / 4;
    int npairs = B >> 1;                          // B is even (2^20)

    qml_precompute<<<1, 32>>>(w);

    int nsm = 148;
    cudaDeviceGetAttribute(&nsm, cudaDevAttrMultiProcessorCount, 0);
    int grid = nsm * 5;                           // exactly one wave at 5 blocks/SM
    int maxgrid = (npairs + 127) / 128;
    if (grid > maxgrid) grid = maxgrid;
    qml_main<<<grid, 128>>>(x, out, npairs);
}

// round 4
// speedup vs baseline: 1.2667x; 1.1750x over previous
#include <cuda_runtime.h>

typedef unsigned long long u64;
typedef unsigned int u32;

// ---- packed f32x2 helpers ----
__device__ __forceinline__ u64 pk2(float a, float b) {
    u64 r; asm("mov.b64 %0,{%1,%2};" : "=l"(r) : "f"(a), "f"(b)); return r;
}
__device__ __forceinline__ void upk2(u64 v, float& a, float& b) {
    asm("mov.b64 {%0,%1},%2;" : "=f"(a), "=f"(b) : "l"(v));
}
__device__ __forceinline__ u64 f2fma(u64 a, u64 b, u64 c) {
    u64 d; asm("fma.rn.f32x2 %0,%1,%2,%3;" : "=l"(d) : "l"(a), "l"(b), "l"(c)); return d;
}
__device__ __forceinline__ u64 f2mul(u64 a, u64 b) {
    u64 d; asm("mul.rn.f32x2 %0,%1,%2;" : "=l"(d) : "l"(a), "l"(b)); return d;
}
__device__ __forceinline__ u64 f2add(u64 a, u64 b) {
    u64 d; asm("add.rn.f32x2 %0,%1,%2;" : "=l"(d) : "l"(a), "l"(b)); return d;
}
__device__ __forceinline__ float frcp(float a) {
    float r; asm("rcp.approx.f32 %0, %1;" : "=f"(r) : "f"(a)); return r;
}

// Gate params, each float duplicated into both f32x2 lanes (u64).
// [8q+0..7], q=0..3 (layer1, tan form): u00r, u00i, u01i, -u01r, u10r, u10i, u11i, -u11r
//   where U = RZ(w[q,1]) @ RY(w[q,0]);  factor used as v' = U @ (1, -i*tan)^T
// [32+2q], [33+2q], q=0..2: tan(wRY/2), -tan(wRY/2)  (layer2 RY, fast-Givens)
// [40] RYC2 = (cos(w0/2)cos(w1/2)cos(w2/2))^2  (layer-2 RY cos product, squared)
// [41] A3 = cos(w3)   [42] B3 = -2*sin(w3)     (RY3 folded into quadratics)
__device__ __align__(16) u64 g_gpu[48];

__device__ __forceinline__ u64 dupf(float v) {
    u32 b = __float_as_uint(v);
    return ((u64)b << 32) | (u64)b;
}

__global__ void qml_precompute(const float* __restrict__ w) {
    if (threadIdx.x == 0) {
        for (int q = 0; q < 4; q++) {
            float ry = w[q * 2 + 0], rz = w[q * 2 + 1];
            float s, c, zs, zc;
            sincosf(0.5f * ry, &s, &c);
            sincosf(0.5f * rz, &zs, &zc);
            u64* o = g_gpu + q * 8;
            o[0] = dupf(c * zc);     // u00r
            o[1] = dupf(-c * zs);    // u00i
            o[2] = dupf(s * zs);     // u01i
            o[3] = dupf(s * zc);     // -u01r
            o[4] = dupf(s * zc);     // u10r
            o[5] = dupf(s * zs);     // u10i
            o[6] = dupf(c * zs);     // u11i
            o[7] = dupf(-c * zc);    // -u11r
        }
        float cprod = 1.0f;
        for (int q = 0; q < 3; q++) {
            float ry = w[(4 + q) * 2 + 0];
            float s, c;
            sincosf(0.5f * ry, &s, &c);
            float t = s / c;
            cprod *= c;
            g_gpu[32 + 2 * q + 0] = dupf(t);
            g_gpu[32 + 2 * q + 1] = dupf(-t);
        }
        g_gpu[40] = dupf(cprod * cprod);
        {   // qubit-3 RY folded into measurement quadratics
            float ry = w[7 * 2 + 0];
            float s, c;
            sincosf(0.5f * ry, &s, &c);
            g_gpu[41] = dupf(c * c - s * s);   // cos(w3)
            g_gpu[42] = dupf(-4.0f * c * s);   // -2 sin(w3)
        }
    }
}

__global__ void __launch_bounds__(128)
qml_main(const float* __restrict__ x, float* __restrict__ out, int npairs) {
    int idx = blockIdx.x * blockDim.x + threadIdx.x;
    if (idx >= npairs) return;

    const u64 m1 = 0xBF800000BF800000ULL;  // {-1.0f, -1.0f}
    const float4* xg = reinterpret_cast<const float4*>(x);
    float4* o4 = reinterpret_cast<float4*>(out);

    float4 xa = xg[2 * idx];
    float4 xb = xg[2 * idx + 1];

    // ---- per-sample half-angle sin/cos + tan (tan shared by both RX layers) ----
    float caA[4], saA[4], caB[4], saB[4];
    __sincosf(0.5f * xa.x, &saA[0], &caA[0]);
    __sincosf(0.5f * xa.y, &saA[1], &caA[1]);
    __sincosf(0.5f * xa.z, &saA[2], &caA[2]);
    __sincosf(0.5f * xa.w, &saA[3], &caA[3]);
    __sincosf(0.5f * xb.x, &saB[0], &caB[0]);
    __sincosf(0.5f * xb.y, &saB[1], &caB[1]);
    __sincosf(0.5f * xb.z, &saB[2], &caB[2]);
    __sincosf(0.5f * xb.w, &saB[3], &caB[3]);

    u64 tx[4], ntx[4];
    u64 gc;  // prod of cos over 4 qubits, per lane
    {
        u64 c0 = pk2(caA[0], caB[0]);
        u64 c1 = pk2(caA[1], caB[1]);
        u64 c2 = pk2(caA[2], caB[2]);
        u64 c3 = pk2(caA[3], caB[3]);
        gc = f2mul(f2mul(c0, c1), f2mul(c2, c3));
#pragma unroll
        for (int q = 0; q < 4; q++) {
            u64 s2 = pk2(saA[q], saB[q]);
            u64 r2 = pk2(frcp(caA[q]), frcp(caB[q]));
            tx[q]  = f2mul(s2, r2);
            ntx[q] = f2mul(tx[q], m1);
        }
    }
    // global probability scale: (gc^2 * RYC)^2 = gc^4 * RYC^2
    u64 g2t;
    {
        u64 gc2 = f2mul(gc, gc);
        g2t = f2mul(f2mul(gc2, gc2), g_gpu[40]);
    }

    // ---- layer-1 single-qubit factors (tan form): v' = U @ (1, -i t)^T ----
    u64 vr[4][2], vi[4][2];
#pragma unroll
    for (int q = 0; q < 4; q++) {
        const u64* u = g_gpu + q * 8;
        vr[q][0] = f2fma(tx[q], u[2], u[0]);
        vi[q][0] = f2fma(tx[q], u[3], u[1]);
        vr[q][1] = f2fma(tx[q], u[6], u[4]);
        vi[q][1] = f2fma(tx[q], u[7], u[5]);
    }

    // ==== Layer-2 RX gates commuted backward through layer-1's CNOTs:
    //   RX3 stays; RX2->RXX(2,3); RX1->RXX(1,2); RX0->RXX(0,1).
    //   All in tan form (cos factors folded into g2t). ====

    // RX(x3)/c on qubit-3 factor: n_k = a_k - i t a_{k^1}
    u64 wr[2], wi[2];
    wr[0] = f2fma(tx[3],  vi[3][1], vr[3][0]);
    wi[0] = f2fma(ntx[3], vr[3][1], vi[3][0]);
    wr[1] = f2fma(tx[3],  vi[3][0], vr[3][1]);
    wi[1] = f2fma(ntx[3], vr[3][0], vi[3][1]);

    // Psi23 = v2' (x) w, then RXX(x2)/c (mask 3)
    u64 Qr[4], Qi[4];
    {
        u64 Pr[4], Pi[4];
        u64 nv2i0 = f2mul(vi[2][0], m1), nv2i1 = f2mul(vi[2][1], m1);
#pragma unroll
        for (int a = 0; a < 2; a++) {
            u64 ar = vr[2][a], ai = vi[2][a], nai = (a == 0) ? nv2i0 : nv2i1;
#pragma unroll
            for (int b = 0; b < 2; b++) {
                int j = a * 2 + b;
                Pr[j] = f2fma(nai, wi[b], f2mul(ar, wr[b]));
                Pi[j] = f2fma(ai,  wr[b], f2mul(ar, wi[b]));
            }
        }
#pragma unroll
        for (int k = 0; k < 4; k++) {
            Qr[k] = f2fma(tx[2],  Pi[k ^ 3], Pr[k]);
            Qi[k] = f2fma(ntx[2], Pr[k ^ 3], Pi[k]);
        }
    }

    // Phi123 = v1' (x) Q, then RXX(x1)/c (mask 6). Fused pairwise.
    u64 Fr[8], Fi[8];
    {
        u64 nv1i0 = f2mul(vi[1][0], m1), nv1i1 = f2mul(vi[1][1], m1);
#pragma unroll
        for (int j = 0; j < 4; j++) {
            int j2 = j ^ 6;
            int t1 = j & 3, t2 = j2 & 3;   // a1=0, a2=1
            u64 p1r = f2fma(nv1i0,    Qi[t1], f2mul(vr[1][0], Qr[t1]));
            u64 p1i = f2fma(vi[1][0], Qr[t1], f2mul(vr[1][0], Qi[t1]));
            u64 p2r = f2fma(nv1i1,    Qi[t2], f2mul(vr[1][1], Qr[t2]));
            u64 p2i = f2fma(vi[1][1], Qr[t2], f2mul(vr[1][1], Qi[t2]));
            Fr[j]  = f2fma(tx[1],  p2i, p1r);
            Fi[j]  = f2fma(ntx[1], p2r, p1i);
            Fr[j2] = f2fma(tx[1],  p1i, p2r);
            Fi[j2] = f2fma(ntx[1], p1r, p2i);
        }
    }

    // Full state = v0' (x) F, then RXX(x0)/c (mask 12). Fused pairwise.
    u64 re[16], im[16];
    {
        u64 nv0i0 = f2mul(vi[0][0], m1), nv0i1 = f2mul(vi[0][1], m1);
#pragma unroll
        for (int t = 0; t < 8; t++) {
            int k1 = t;
            int k2 = 8 + (t ^ 4);
            int t2 = t ^ 4;
            u64 p1r = f2fma(nv0i0,    Fi[t],  f2mul(vr[0][0], Fr[t]));
            u64 p1i = f2fma(vi[0][0], Fr[t],  f2mul(vr[0][0], Fi[t]));
            u64 p2r = f2fma(nv0i1,    Fi[t2], f2mul(vr[0][1], Fr[t2]));
            u64 p2i = f2fma(vi[0][1], Fr[t2], f2mul(vr[0][1], Fi[t2]));
            re[k1] = f2fma(tx[0],  p2i, p1r);
            im[k1] = f2fma(ntx[0], p2r, p1i);
            re[k2] = f2fma(tx[0],  p1i, p2r);
            im[k2] = f2fma(ntx[0], p1r, p2i);
        }
    }

    // ---- layer-1 CNOT chain: basis permutation (register renames) ----
#pragma unroll
    for (int c = 0; c < 3; c++) {
        int bcm = 8 >> c, btm = 8 >> (c + 1);
#pragma unroll
        for (int k = 0; k < 16; k++)
            if ((k & bcm) && !(k & btm)) {
                u64 tr = re[k]; re[k] = re[k | btm]; re[k | btm] = tr;
                u64 ti = im[k]; im[k] = im[k | btm]; im[k | btm] = ti;
            }
    }

    // ---- layer-2 RY qubits 0..2, fast-Givens: n0 = a0 - t a1; n1 = t a0 + a1 ----
#pragma unroll
    for (int q = 0; q < 3; q++) {
        int bq = 8 >> q;
        u64 tq  = g_gpu[32 + 2 * q + 0];
        u64 ntq = g_gpu[32 + 2 * q + 1];
#pragma unroll
        for (int k = 0; k < 16; k++)
            if (!(k & bq)) {
                int k1 = k | bq;
                u64 n0r = f2fma(ntq, re[k1], re[k]);
                u64 n0i = f2fma(ntq, im[k1], im[k]);
                u64 n1r = f2fma(tq, re[k], re[k1]);
                u64 n1i = f2fma(tq, im[k], im[k1]);
                re[k] = n0r; im[k] = n0i; re[k1] = n1r; im[k1] = n1i;
            }
    }

    // ---- quadratics with RY3 fold + global scale g2t:
    //   s01 = g2t*(|a0|^2+|a1|^2)
    //   d01 = g2t*[cos(w3)(|a0|^2-|a1|^2) - 2 sin(w3)(r0r1+i0i1)]
    u64 s01[8], d01[8];
    {
        u64 A3g = f2mul(g_gpu[41], g2t);
        u64 B3g = f2mul(g_gpu[42], g2t);
#pragma unroll
        for (int j = 0; j < 8; j++) {
            int k0 = 2 * j, k1 = 2 * j + 1;
            u64 q0 = f2fma(im[k0], im[k0], f2mul(re[k0], re[k0]));
            u64 q1 = f2fma(im[k1], im[k1], f2mul(re[k1], re[k1]));
            u64 xx = f2fma(im[k0], im[k1], f2mul(re[k0], re[k1]));
            s01[j] = f2mul(g2t, f2add(q0, q1));
            u64 z  = f2fma(q1, m1, q0);
            d01[j] = f2fma(B3g, xx, f2mul(A3g, z));
        }
    }

    // ---- layer-2 CNOTs folded into measurement parities (Walsh) ----
    u64 z3p = f2add(f2add(d01[0], d01[3]), f2add(d01[5], d01[6]));
    u64 z3m = f2add(f2add(d01[1], d01[2]), f2add(d01[4], d01[7]));
    u64 Z3 = f2fma(z3m, m1, z3p);

    u64 sq[4], dq[4];
#pragma unroll
    for (int m = 0; m < 4; m++) {
        sq[m] = f2add(s01[2 * m], s01[2 * m + 1]);
        dq[m] = f2fma(s01[2 * m + 1], m1, s01[2 * m]);
    }
    u64 Z2 = f2fma(f2add(dq[1], dq[2]), m1, f2add(dq[0], dq[3]));
    u64 Z1 = f2fma(f2add(sq[1], sq[2]), m1, f2add(sq[0], sq[3]));
    u64 Z0 = f2fma(f2add(sq[2], sq[3]), m1, f2add(sq[0], sq[1]));

    // ---- unpack lanes and store ----
    float z0a, z0b, z1a, z1b, z2a, z2b, z3a, z3b;
    upk2(Z0, z0a, z0b); upk2(Z1, z1a, z1b);
    upk2(Z2, z2a, z2b); upk2(Z3, z3a, z3b);
    o4[2 * idx]     = make_float4(z0a, z1a, z2a, z3a);
    o4[2 * idx + 1] = make_float4(z0b, z1b, z2b, z3b);
}

extern "C" void kernel_launch(void* const* d_in, const int* in_sizes, int n_in,
                              void* d_out, int out_size) {
    const float* x = (const float*)d_in[0];       // [B,4] float32
    const float* w = (const float*)d_in[1];       // [2,4,2] float32
    float* out = (float*)d_out;                   // [B,4] float32
    int B = in_sizes[0] / 4;
    int npairs = B >> 1;                          // B = 2^20, even

    qml_precompute<<<1, 32>>>(w);

    int block = 128;
    int grid = (npairs + block - 1) / block;
    qml_main<<<grid, block>>>(x, out, npairs);
}